// round 5
// baseline (speedup 1.0000x reference)
#include <cuda_runtime.h>
#include <cuda_bf16.h>
#include <math.h>

// Problem constants
#define BB 2
#define LL 192
#define HH 512
#define NHH 8
#define DPHH 64
#define MAXLEN 512
#define NDELTA 383   // deltas -191..191
#define BL (BB*LL)   // 384

// ---------------- device scratch (no allocation allowed) ----------------
__device__ float g_q [BL*HH];
__device__ float g_k [BL*HH];
__device__ float g_v [BL*HH];
__device__ float g_qv[BL*HH];
__device__ float g_qu[BL*HH];
__device__ __nv_bfloat16 g_gt[4*NDELTA*HH];   // 4 tables [383][512] bf16
__device__ __nv_bfloat16 g_wt[BL*NHH*HH];     // W~ [bq][n][f] bf16
__device__ float g_cd[BL*NHH];                // constD
__device__ float g_sa[BB*NHH*LL*LL];          // scoresA (A+C term) [b][n][q][k]
__device__ float g_at[BB*NHH*LL*LL];          // attn weights [b][n][q][k]
__device__ float g_x [BL*HH];                 // pre-FF output

// ---------------- f32x2 packed helpers (Blackwell) ----------------
__device__ __forceinline__ void fma2(unsigned long long& d,
                                     unsigned long long a,
                                     unsigned long long b) {
    asm("fma.rn.f32x2 %0, %1, %2, %0;" : "+l"(d) : "l"(a), "l"(b));
}
__device__ __forceinline__ unsigned long long pk2(float x, float y) {
    unsigned long long r;
    asm("mov.b64 %0, {%1,%2};" : "=l"(r) : "f"(x), "f"(y));
    return r;
}
__device__ __forceinline__ float2 upk2(unsigned long long v) {
    float x, y;
    asm("mov.b64 {%0,%1}, %2;" : "=f"(x), "=f"(y) : "l"(v));
    return make_float2(x, y);
}

// ---------------- generic batched strided SGEMM ----------------
// C[m,n] = sum_k A[m*a_sm + k*a_sk] * B[n*b_sn + k*b_sk] + bias[n]
// Tile: 32 rows x 64 cols, 256 threads, 2x4 micro-tile (f32x2),
// register-prefetch double buffering, A splatted in smem to feed f32x2
// without pack movs. K must be a multiple of 16 (true for all uses).
struct GemmDesc {
    const float* A;
    const float* B;
    const float* bias;
    void*        C;
    int a_sm, a_sk, b_sn, b_sk, c_sm, M, N, K, bf16;
};
struct DescArr24 { GemmDesc d[24]; };

__global__ void __launch_bounds__(256) sgemm_b(DescArr24 gd)
{
    const GemmDesc dsc = gd.d[blockIdx.z];
    const int row0 = blockIdx.y << 5;     // 32-row tiles
    const int col0 = blockIdx.x << 6;     // 64-col tiles
    if (row0 >= dsc.M || col0 >= dsc.N) return;

    __shared__ __align__(16) float2 As2[16][33];   // A splatted (a,a)
    __shared__ __align__(16) float  Bs[16][68];

    const int t  = threadIdx.x;
    const int tx = t & 15, ty = t >> 4;

    const int a_kk0 = t & 15, a_mm0 = t >> 4;      // 2 A elems / thread
    const int a_mm1 = a_mm0 + 16;
    const int b_kk0 = t & 15, b_nn0 = t >> 4;      // 4 B elems / thread
    const int am0ok = (row0 + a_mm0) < dsc.M;
    const int am1ok = (row0 + a_mm1) < dsc.M;
    const float* Aad0 = dsc.A + (size_t)(row0 + a_mm0) * dsc.a_sm + (size_t)a_kk0 * dsc.a_sk;
    const float* Aad1 = dsc.A + (size_t)(row0 + a_mm1) * dsc.a_sm + (size_t)a_kk0 * dsc.a_sk;
    const float* Bad[4];
    int bok[4];
    #pragma unroll
    for (int i = 0; i < 4; i++) {
        int nn = b_nn0 + 16 * i;
        bok[i] = (col0 + nn) < dsc.N;
        Bad[i] = dsc.B + (size_t)(col0 + nn) * dsc.b_sn + (size_t)b_kk0 * dsc.b_sk;
    }
    const size_t aK = (size_t)dsc.a_sk * 16;
    const size_t bK = (size_t)dsc.b_sk * 16;

    unsigned long long acc2[2][2] = {{0ULL, 0ULL}, {0ULL, 0ULL}};

    // prefetch chunk 0
    float a_r[2], b_r[4];
    a_r[0] = am0ok ? *Aad0 : 0.f;
    a_r[1] = am1ok ? *Aad1 : 0.f;
    #pragma unroll
    for (int i = 0; i < 4; i++) b_r[i] = bok[i] ? *Bad[i] : 0.f;

    for (int k0 = 0; k0 < dsc.K; k0 += 16) {
        As2[a_kk0][a_mm0] = make_float2(a_r[0], a_r[0]);
        As2[a_kk0][a_mm1] = make_float2(a_r[1], a_r[1]);
        #pragma unroll
        for (int i = 0; i < 4; i++) Bs[b_kk0][b_nn0 + 16 * i] = b_r[i];
        __syncthreads();

        if (k0 + 16 < dsc.K) {
            Aad0 += aK; Aad1 += aK;
            a_r[0] = am0ok ? *Aad0 : 0.f;
            a_r[1] = am1ok ? *Aad1 : 0.f;
            #pragma unroll
            for (int i = 0; i < 4; i++) {
                Bad[i] += bK;
                b_r[i] = bok[i] ? *Bad[i] : 0.f;
            }
        }

        #pragma unroll
        for (int kk = 0; kk < 16; kk++) {
            unsigned long long a0 =
                *reinterpret_cast<const unsigned long long*>(&As2[kk][ty << 1]);
            unsigned long long a1 =
                *reinterpret_cast<const unsigned long long*>(&As2[kk][(ty << 1) + 1]);
            ulonglong2 b =
                *reinterpret_cast<const ulonglong2*>(&Bs[kk][tx << 2]);
            fma2(acc2[0][0], a0, b.x);
            fma2(acc2[0][1], a0, b.y);
            fma2(acc2[1][0], a1, b.x);
            fma2(acc2[1][1], a1, b.y);
        }
        __syncthreads();
    }

    #pragma unroll
    for (int im = 0; im < 2; im++) {
        int m = row0 + (ty << 1) + im;
        if (m >= dsc.M) continue;
        #pragma unroll
        for (int jb = 0; jb < 2; jb++) {
            float2 r2 = upk2(acc2[im][jb]);
            int n0 = col0 + (tx << 2) + (jb << 1);
            float rx = r2.x + (dsc.bias ? dsc.bias[n0] : 0.f);
            float ry = r2.y + (dsc.bias ? dsc.bias[n0 + 1] : 0.f);
            if (dsc.bf16) {
                __nv_bfloat16* Cb = (__nv_bfloat16*)dsc.C;
                if (n0     < dsc.N) Cb[(size_t)m * dsc.c_sm + n0]     = __float2bfloat16(rx);
                if (n0 + 1 < dsc.N) Cb[(size_t)m * dsc.c_sm + n0 + 1] = __float2bfloat16(ry);
            } else {
                float* Cf = (float*)dsc.C;
                if (n0     < dsc.N) Cf[(size_t)m * dsc.c_sm + n0]     = rx;
                if (n0 + 1 < dsc.N) Cf[(size_t)m * dsc.c_sm + n0 + 1] = ry;
            }
        }
    }
}

// ---------------- fused qv/qu/constD kernel ----------------
__global__ void qvqucd_kernel(const float* __restrict__ q,
                              const float* __restrict__ vbias,
                              const float* __restrict__ ubias,
                              const float* __restrict__ br,
                              float* __restrict__ qv,
                              float* __restrict__ qu,
                              float* __restrict__ cd)
{
    const int bq = blockIdx.x;
    const int t  = threadIdx.x;
    float qx  = q[bq * 512 + t];
    float qvv = qx + vbias[t];
    qv[bq * 512 + t] = qvv;
    qu[bq * 512 + t] = qx + ubias[t];

    __shared__ float s[512];
    s[t] = qvv * br[t];
    __syncthreads();

    const int w = t >> 5, lane = t & 31;
    if (w < 8) {
        float v = s[w * 64 + lane] + s[w * 64 + 32 + lane];
        #pragma unroll
        for (int sh = 16; sh > 0; sh >>= 1)
            v += __shfl_xor_sync(0xffffffffu, v, sh);
        if (lane == 0) cd[bq * 8 + w] = v;
    }
}

// ---------------- fused score kernel: one CTA per (b, q) ----------------
// Computes softmax attention weights and stores them to gmem [b][n][q][k].
// Warp layout: lane = (kq:2bits)(fq:3bits); 4 keys per warp iteration,
// 8 lanes per key splitting the 512-f dot.
__global__ void __launch_bounds__(256, 4) attn_kernel(
    const __nv_bfloat16* __restrict__ gtab,
    const __nv_bfloat16* __restrict__ wt,
    const float* __restrict__ sabuf,
    const float* __restrict__ cdg,
    const int*   __restrict__ pos_s,
    const int*   __restrict__ pos_e,
    const int*   __restrict__ seq_len,
    float* __restrict__ atbuf)
{
    const int BQ = blockIdx.x;            // 0..383
    const int b  = BQ / LL;
    const int qi = BQ - b * LL;

    __shared__ __align__(16) __nv_bfloat16 wts[8][512];   // W~ bf16, 8KB
    __shared__ float sc[8][192];          // rel score
    __shared__ float sA[8][192];          // precomputed (A + C)
    __shared__ int   ps[192], pev[192];
    __shared__ float cd[8];

    const int tid  = threadIdx.x;
    const int warp = tid >> 5;
    const int lane = tid & 31;

    // load W~ (4096 bf16 = 512 uint4)
    {
        const uint4* src = (const uint4*)(wt + (size_t)BQ * 4096);
        uint4* dst = (uint4*)&wts[0][0];
        for (int e = tid; e < 512; e += 256) dst[e] = src[e];
    }
    {
        const size_t sabase = (size_t)b * 8 * 36864 + (size_t)qi * 192;
        for (int e = tid; e < 1536; e += 256) {
            int n = e / 192;
            int k = e - n * 192;
            sA[n][k] = sabuf[sabase + (size_t)n * 36864 + k];
        }
    }
    if (tid < 192) { ps[tid] = pos_s[b * LL + tid]; pev[tid] = pos_e[b * LL + tid]; }
    if (tid < 8)   cd[tid] = cdg[BQ * 8 + tid];
    __syncthreads();

    const int sq = ps[qi], eq = pev[qi];
    const int slen = seq_len[b];

    const __nv_bfloat16* g0 = gtab;
    const __nv_bfloat16* g1 = gtab + 1 * NDELTA * 512;
    const __nv_bfloat16* g2 = gtab + 2 * NDELTA * 512;
    const __nv_bfloat16* g3 = gtab + 3 * NDELTA * 512;

    const int kq = lane >> 3;       // 0..3
    const int fq = lane & 7;        // 0..7
    const int fb = fq << 3;         // bf16 element offset within a 64-elem chunk
    const __nv_bfloat162 zz = __float2bfloat162_rn(0.f);
    const uint4* wrow = (const uint4*)&wts[0][0];   // 64 uint4 per head row

    const int kbeg = warp * 24;
    for (int k0 = kbeg; k0 < kbeg + 24; k0 += 4) {
        if (k0 >= slen) continue;   // warp-uniform; masked region never read
        const int k = k0 + kq;
        const int sk = ps[k], ek = pev[k];
        const __nv_bfloat16* r0 = g0 + (((sq - sk + 191) << 9) + fb);
        const __nv_bfloat16* r1 = g1 + (((sq - ek + 191) << 9) + fb);
        const __nv_bfloat16* r2 = g2 + (((eq - sk + 191) << 9) + fb);
        const __nv_bfloat16* r3 = g3 + (((eq - ek + 191) << 9) + fb);

        __nv_bfloat162 acc[8];
        #pragma unroll
        for (int n = 0; n < 8; n++) acc[n] = zz;

        #pragma unroll 2
        for (int c = 0; c < 8; c++) {
            uint4 u0 = *(const uint4*)(r0 + (c << 6));
            uint4 u1 = *(const uint4*)(r1 + (c << 6));
            uint4 u2 = *(const uint4*)(r2 + (c << 6));
            uint4 u3 = *(const uint4*)(r3 + (c << 6));
            const __nv_bfloat162* A2 = (const __nv_bfloat162*)&u0;
            const __nv_bfloat162* B2 = (const __nv_bfloat162*)&u1;
            const __nv_bfloat162* C2 = (const __nv_bfloat162*)&u2;
            const __nv_bfloat162* D2 = (const __nv_bfloat162*)&u3;
            __nv_bfloat162 z[4];
            #pragma unroll
            for (int j = 0; j < 4; j++)
                z[j] = __hmax2(__hadd2(__hadd2(A2[j], B2[j]),
                                       __hadd2(C2[j], D2[j])), zz);
            #pragma unroll
            for (int n = 0; n < 8; n++) {
                uint4 w = wrow[(n << 6) + (c << 3) + fq];
                const __nv_bfloat162* W2 = (const __nv_bfloat162*)&w;
                acc[n] = __hfma2(z[0], W2[0], acc[n]);
                acc[n] = __hfma2(z[1], W2[1], acc[n]);
                acc[n] = __hfma2(z[2], W2[2], acc[n]);
                acc[n] = __hfma2(z[3], W2[3], acc[n]);
            }
        }

        #pragma unroll
        for (int n = 0; n < 8; n++) {
            float2 f2 = __bfloat1622float2(acc[n]);
            float s = f2.x + f2.y;
            s += __shfl_xor_sync(0xffffffffu, s, 4);
            s += __shfl_xor_sync(0xffffffffu, s, 2);
            s += __shfl_xor_sync(0xffffffffu, s, 1);
            if (fq == 0) sc[n][k] = s;
        }
    }
    __syncthreads();

    // softmax: warp n handles head n over 192 keys (6 per lane);
    // write normalized weights straight to gmem [b][n][q][k].
    {
        float vals[6];
        float mx = -1e30f;
        #pragma unroll
        for (int j = 0; j < 6; j++) {
            int k = lane + (j << 5);
            float v = (sc[warp][k] + sA[warp][k] + cd[warp]) * 0.125f;
            v = (k < slen) ? v : -1e30f;
            vals[j] = v;
            mx = fmaxf(mx, v);
        }
        #pragma unroll
        for (int s = 16; s > 0; s >>= 1)
            mx = fmaxf(mx, __shfl_xor_sync(0xffffffffu, mx, s));
        float se = 0.f;
        float ev[6];
        #pragma unroll
        for (int j = 0; j < 6; j++) {
            ev[j] = (vals[j] > -1e29f) ? __expf(vals[j] - mx) : 0.f;
            se += ev[j];
        }
        #pragma unroll
        for (int s = 16; s > 0; s >>= 1)
            se += __shfl_xor_sync(0xffffffffu, se, s);
        float inv = 1.f / se;
        float* arow = atbuf + ((size_t)(b * 8 + warp) * 192 + qi) * 192;
        #pragma unroll
        for (int j = 0; j < 6; j++)
            arow[lane + (j << 5)] = ev[j] * inv;
    }
}

// ---------------- launch ----------------
extern "C" void kernel_launch(void* const* d_in, const int* in_sizes, int n_in,
                              void* d_out, int out_size)
{
    // optional scalar lex_num at index 4
    int off = (n_in > 4 && in_sizes[4] == 1) ? 1 : 0;

    const float* key   = (const float*)d_in[0];
    const float* query = (const float*)d_in[1];
    const float* value = (const float*)d_in[2];
    const int*   seqlp = (const int*)  d_in[3];
    const int*   pos_s = (const int*)  d_in[4 + off];
    const int*   pos_e = (const int*)  d_in[5 + off];
    const float* pe    = (const float*)d_in[6 + off];
    const float* W_fus = (const float*)d_in[7 + off];
    const float* b_fus = (const float*)d_in[8 + off];
    const float* Wk    = (const float*)d_in[9 + off];
    const float* bk    = (const float*)d_in[10 + off];
    const float* Wq    = (const float*)d_in[11 + off];
    const float* bq    = (const float*)d_in[12 + off];
    const float* Wv    = (const float*)d_in[13 + off];
    const float* bv    = (const float*)d_in[14 + off];
    const float* Wr    = (const float*)d_in[15 + off];
    const float* br    = (const float*)d_in[16 + off];
    const float* ub    = (const float*)d_in[17 + off];
    const float* vb    = (const float*)d_in[18 + off];
    const float* Wff   = (const float*)d_in[19 + off];
    const float* bff   = (const float*)d_in[20 + off];
    float* out = (float*)d_out;

    float *p_q, *p_k, *p_v, *p_qv, *p_qu, *p_cd, *p_sa, *p_at, *p_x;
    __nv_bfloat16 *p_gt, *p_wt;
    cudaGetSymbolAddress((void**)&p_q,  g_q);
    cudaGetSymbolAddress((void**)&p_k,  g_k);
    cudaGetSymbolAddress((void**)&p_v,  g_v);
    cudaGetSymbolAddress((void**)&p_qv, g_qv);
    cudaGetSymbolAddress((void**)&p_qu, g_qu);
    cudaGetSymbolAddress((void**)&p_gt, g_gt);
    cudaGetSymbolAddress((void**)&p_wt, g_wt);
    cudaGetSymbolAddress((void**)&p_cd, g_cd);
    cudaGetSymbolAddress((void**)&p_sa, g_sa);
    cudaGetSymbolAddress((void**)&p_at, g_at);
    cudaGetSymbolAddress((void**)&p_x,  g_x);

    // 1) combined: q/k/v projections (K=512) + 4 delta tables (K=256, bf16 out)
    {
        DescArr24 gd = {};
        const float* Aq[3]  = {query, key, value};
        const float* Wq3[3] = {Wq, Wk, Wv};
        const float* bq3[3] = {bq, bk, bv};
        float* Cq[3] = {p_q, p_k, p_v};
        for (int i = 0; i < 3; i++) {
            gd.d[i] = {Aq[i], Wq3[i], bq3[i], Cq[i],
                       512, 1, 512, 1, 512, BL, 512, 512, 0};
        }
        // g_t[di][f] = pe[di+321, :256] . W_fus[f, t*256 : (t+1)*256] (+b_fus on t=0)
        for (int t = 0; t < 4; t++) {
            gd.d[3 + t] = {pe + 321 * 512, W_fus + t * 256,
                           (t == 0) ? b_fus : nullptr,
                           p_gt + (size_t)t * NDELTA * 512,
                           512, 1, 1024, 1, 512, NDELTA, 512, 256, 1};
        }
        sgemm_b<<<dim3(8, 12, 7), 256>>>(gd);
    }

    // 2) fused qv = q+v_bias, qu = q+u_bias, constD = qv.br per head
    qvqucd_kernel<<<BL, 512>>>(p_q, vb, ub, br, p_qv, p_qu, p_cd);

    // 3) combined: W~ (8 descs, bf16 out) + scoresA (16 descs)
    {
        DescArr24 gd = {};
        // W~[bq,n,f] = sum_d qv[bq, n*64+d] * Wr[n*64+d, f]
        for (int nh = 0; nh < 8; nh++) {
            gd.d[nh] = {p_qv + nh * 64, Wr + (size_t)nh * 64 * 512, nullptr,
                        p_wt + nh * 512,
                        512, 1, 1, 512, 4096, BL, 512, 64, 1};
        }
        // scoresA[b,n,q,k] = sum_d qu[b,q,n*64+d] * k[b,k,n*64+d]
        for (int b2 = 0; b2 < 2; b2++) {
            for (int nh = 0; nh < 8; nh++) {
                int z = 8 + b2 * 8 + nh;
                gd.d[z] = {p_qu + (size_t)b2 * LL * 512 + nh * 64,
                           p_k  + (size_t)b2 * LL * 512 + nh * 64,
                           nullptr,
                           p_sa + (size_t)(b2 * 8 + nh) * LL * LL,
                           512, 1, 512, 1, LL, LL, LL, 64, 0};
            }
        }
        sgemm_b<<<dim3(8, 12, 24), 256>>>(gd);
    }

    // 4) fused score kernel: bf16 gathers + bf16 W~ dot + softmax -> attn wts
    attn_kernel<<<BL, 256>>>(p_gt, p_wt, p_sa, p_cd,
                             pos_s, pos_e, seqlp, p_at);

    // 5) attn@v as 16 batched GEMMs: x[q, n*64+f] = attn_n[q,:] . v[:, n*64+f]
    {
        DescArr24 gd = {};
        for (int b2 = 0; b2 < 2; b2++) {
            for (int nh = 0; nh < 8; nh++) {
                int z = b2 * 8 + nh;
                gd.d[z] = {p_at + (size_t)(b2 * 8 + nh) * LL * LL,
                           p_v + (size_t)b2 * LL * 512 + nh * 64,
                           nullptr,
                           p_x + (size_t)b2 * LL * 512 + nh * 64,
                           LL, 1, 1, 512, 512, LL, 64, LL, 0};
            }
        }
        sgemm_b<<<dim3(1, 6, 16), 256>>>(gd);
    }

    // 6) final: out = X @ Wff^T + bff
    {
        DescArr24 gd = {};
        gd.d[0] = {p_x, Wff, bff, out, 512, 1, 512, 1, 512, BL, 512, 512, 0};
        sgemm_b<<<dim3(8, 12, 1), 256>>>(gd);
    }
}

// round 6
// speedup vs baseline: 1.1875x; 1.1875x over previous
#include <cuda_runtime.h>
#include <cuda_bf16.h>
#include <math.h>

// Problem constants
#define BB 2
#define LL 192
#define HH 512
#define NHH 8
#define DPHH 64
#define MAXLEN 512
#define NDELTA 383   // deltas -191..191
#define BL (BB*LL)   // 384

// ---------------- device scratch (no allocation allowed) ----------------
__device__ float g_q [BL*HH];
__device__ float g_k [BL*HH];
__device__ float g_v [BL*HH];
__device__ float g_qv[BL*HH];
__device__ float g_qu[BL*HH];
__device__ __nv_bfloat16 g_gt[4*NDELTA*HH];   // 4 tables [383][512] bf16
__device__ __nv_bfloat16 g_wt[BL*NHH*HH];     // W~ [bq][n][f] bf16
__device__ float g_cd[BL*NHH];                // constD
__device__ float g_sa[BB*NHH*LL*LL];          // scoresA (A+C term) [b][n][q][k]
__device__ float g_at[BB*NHH*LL*LL];          // attn weights [b][n][q][k]
__device__ float g_x [BL*HH];                 // pre-FF output

// ---------------- f32x2 packed helpers (Blackwell) ----------------
__device__ __forceinline__ void fma2(unsigned long long& d,
                                     unsigned long long a,
                                     unsigned long long b) {
    asm("fma.rn.f32x2 %0, %1, %2, %0;" : "+l"(d) : "l"(a), "l"(b));
}
__device__ __forceinline__ unsigned long long pk2(float x, float y) {
    unsigned long long r;
    asm("mov.b64 %0, {%1,%2};" : "=l"(r) : "f"(x), "f"(y));
    return r;
}
__device__ __forceinline__ float2 upk2(unsigned long long v) {
    float x, y;
    asm("mov.b64 {%0,%1}, %2;" : "=f"(x), "=f"(y) : "l"(v));
    return make_float2(x, y);
}

// ---------------- generic batched strided SGEMM ----------------
// C[m,n] = sum_k A[m*a_sm + k*a_sk] * B[n*b_sn + k*b_sk] + bias[n]
// Tile: 32 rows x 64 cols, 256 threads, 2x4 micro-tile (f32x2),
// register-prefetch double buffering. K must be a multiple of 16.
// bswap=1 flips the B smem-fill mapping to n-fastest (coalesced when b_sn==1).
struct GemmDesc {
    const float* A;
    const float* B;
    const float* bias;
    void*        C;
    int a_sm, a_sk, b_sn, b_sk, c_sm, M, N, K, bf16, bswap;
};
struct DescArr24 { GemmDesc d[24]; };

__global__ void __launch_bounds__(256) sgemm_b(DescArr24 gd)
{
    const GemmDesc dsc = gd.d[blockIdx.z];
    const int row0 = blockIdx.y << 5;     // 32-row tiles
    const int col0 = blockIdx.x << 6;     // 64-col tiles
    if (row0 >= dsc.M || col0 >= dsc.N) return;

    __shared__ __align__(16) float As[16][34];
    __shared__ __align__(16) float Bs[16][68];

    const int t  = threadIdx.x;
    const int tx = t & 15, ty = t >> 4;

    // A-load mapping: element e in [0,512): kk=e&15, mm=e>>4 (2 per thread)
    const int a_kk0 = t & 15, a_mm0 = t >> 4;
    const int a_mm1 = a_mm0 + 16;
    const int am0ok = (row0 + a_mm0) < dsc.M;
    const int am1ok = (row0 + a_mm1) < dsc.M;
    const float* Aad0 = dsc.A + (size_t)(row0 + a_mm0) * dsc.a_sm + (size_t)a_kk0 * dsc.a_sk;
    const float* Aad1 = dsc.A + (size_t)(row0 + a_mm1) * dsc.a_sm + (size_t)a_kk0 * dsc.a_sk;

    // B-load mapping: 4 elements per thread, e = t + 256*i.
    // default: kk=e&15, nn=e>>4 (coalesced when b_sk==1)
    // bswap:   kk=e>>6, nn=e&63 (coalesced when b_sn==1)
    int b_kk[4], b_nn[4], bok[4];
    const float* Bad[4];
    #pragma unroll
    for (int i = 0; i < 4; i++) {
        int e = t + 256 * i;
        int kk = dsc.bswap ? (e >> 6) : (e & 15);
        int nn = dsc.bswap ? (e & 63) : (e >> 4);
        b_kk[i] = kk; b_nn[i] = nn;
        bok[i] = (col0 + nn) < dsc.N;
        Bad[i] = dsc.B + (size_t)(col0 + nn) * dsc.b_sn + (size_t)kk * dsc.b_sk;
    }
    const size_t aK = (size_t)dsc.a_sk * 16;
    const size_t bK = (size_t)dsc.b_sk * 16;

    unsigned long long acc2[2][2] = {{0ULL, 0ULL}, {0ULL, 0ULL}};

    // prefetch chunk 0
    float a_r[2], b_r[4];
    a_r[0] = am0ok ? *Aad0 : 0.f;
    a_r[1] = am1ok ? *Aad1 : 0.f;
    #pragma unroll
    for (int i = 0; i < 4; i++) b_r[i] = bok[i] ? *Bad[i] : 0.f;

    for (int k0 = 0; k0 < dsc.K; k0 += 16) {
        As[a_kk0][a_mm0] = a_r[0];
        As[a_kk0][a_mm1] = a_r[1];
        #pragma unroll
        for (int i = 0; i < 4; i++) Bs[b_kk[i]][b_nn[i]] = b_r[i];
        __syncthreads();

        if (k0 + 16 < dsc.K) {
            Aad0 += aK; Aad1 += aK;
            a_r[0] = am0ok ? *Aad0 : 0.f;
            a_r[1] = am1ok ? *Aad1 : 0.f;
            #pragma unroll
            for (int i = 0; i < 4; i++) {
                Bad[i] += bK;
                b_r[i] = bok[i] ? *Bad[i] : 0.f;
            }
        }

        #pragma unroll
        for (int kk = 0; kk < 16; kk++) {
            float2 a2 = *(const float2*)&As[kk][ty << 1];
            float4 b4 = *(const float4*)&Bs[kk][tx << 2];
            unsigned long long b01 = pk2(b4.x, b4.y);
            unsigned long long b23 = pk2(b4.z, b4.w);
            unsigned long long ax = pk2(a2.x, a2.x);
            unsigned long long ay = pk2(a2.y, a2.y);
            fma2(acc2[0][0], ax, b01);
            fma2(acc2[0][1], ax, b23);
            fma2(acc2[1][0], ay, b01);
            fma2(acc2[1][1], ay, b23);
        }
        __syncthreads();
    }

    #pragma unroll
    for (int im = 0; im < 2; im++) {
        int m = row0 + (ty << 1) + im;
        if (m >= dsc.M) continue;
        #pragma unroll
        for (int jb = 0; jb < 2; jb++) {
            float2 r2 = upk2(acc2[im][jb]);
            int n0 = col0 + (tx << 2) + (jb << 1);
            float rx = r2.x + (dsc.bias ? dsc.bias[n0] : 0.f);
            float ry = r2.y + (dsc.bias ? dsc.bias[n0 + 1] : 0.f);
            if (dsc.bf16) {
                __nv_bfloat16* Cb = (__nv_bfloat16*)dsc.C;
                if (n0     < dsc.N) Cb[(size_t)m * dsc.c_sm + n0]     = __float2bfloat16(rx);
                if (n0 + 1 < dsc.N) Cb[(size_t)m * dsc.c_sm + n0 + 1] = __float2bfloat16(ry);
            } else {
                float* Cf = (float*)dsc.C;
                if (n0     < dsc.N) Cf[(size_t)m * dsc.c_sm + n0]     = rx;
                if (n0 + 1 < dsc.N) Cf[(size_t)m * dsc.c_sm + n0 + 1] = ry;
            }
        }
    }
}

// ---------------- fused qv/qu/constD kernel ----------------
__global__ void qvqucd_kernel(const float* __restrict__ q,
                              const float* __restrict__ vbias,
                              const float* __restrict__ ubias,
                              const float* __restrict__ br,
                              float* __restrict__ qv,
                              float* __restrict__ qu,
                              float* __restrict__ cd)
{
    const int bq = blockIdx.x;
    const int t  = threadIdx.x;
    float qx  = q[bq * 512 + t];
    float qvv = qx + vbias[t];
    qv[bq * 512 + t] = qvv;
    qu[bq * 512 + t] = qx + ubias[t];

    __shared__ float s[512];
    s[t] = qvv * br[t];
    __syncthreads();

    const int w = t >> 5, lane = t & 31;
    if (w < 8) {
        float v = s[w * 64 + lane] + s[w * 64 + 32 + lane];
        #pragma unroll
        for (int sh = 16; sh > 0; sh >>= 1)
            v += __shfl_xor_sync(0xffffffffu, v, sh);
        if (lane == 0) cd[bq * 8 + w] = v;
    }
}

// ---------------- fused score kernel: one CTA per (b, q) ----------------
// Computes softmax attention weights and stores them to gmem [b][n][q][k].
__global__ void __launch_bounds__(256, 4) attn_kernel(
    const __nv_bfloat16* __restrict__ gtab,
    const __nv_bfloat16* __restrict__ wt,
    const float* __restrict__ sabuf,
    const float* __restrict__ cdg,
    const int*   __restrict__ pos_s,
    const int*   __restrict__ pos_e,
    const int*   __restrict__ seq_len,
    float* __restrict__ atbuf)
{
    const int BQ = blockIdx.x;            // 0..383
    const int b  = BQ / LL;
    const int qi = BQ - b * LL;

    __shared__ __align__(16) __nv_bfloat16 wts[8][512];   // W~ bf16, 8KB
    __shared__ float sc[8][192];          // rel score
    __shared__ float sA[8][192];          // precomputed (A + C)
    __shared__ int   ps[192], pev[192];
    __shared__ float cd[8];

    const int tid  = threadIdx.x;
    const int warp = tid >> 5;
    const int lane = tid & 31;

    // load W~ (4096 bf16 = 512 uint4)
    {
        const uint4* src = (const uint4*)(wt + (size_t)BQ * 4096);
        uint4* dst = (uint4*)&wts[0][0];
        for (int e = tid; e < 512; e += 256) dst[e] = src[e];
    }
    {
        const size_t sabase = (size_t)b * 8 * 36864 + (size_t)qi * 192;
        for (int e = tid; e < 1536; e += 256) {
            int n = e / 192;
            int k = e - n * 192;
            sA[n][k] = sabuf[sabase + (size_t)n * 36864 + k];
        }
    }
    if (tid < 192) { ps[tid] = pos_s[b * LL + tid]; pev[tid] = pos_e[b * LL + tid]; }
    if (tid < 8)   cd[tid] = cdg[BQ * 8 + tid];
    __syncthreads();

    const int sq = ps[qi], eq = pev[qi];
    const int slen = seq_len[b];

    const __nv_bfloat16* g0 = gtab;
    const __nv_bfloat16* g1 = gtab + 1 * NDELTA * 512;
    const __nv_bfloat16* g2 = gtab + 2 * NDELTA * 512;
    const __nv_bfloat16* g3 = gtab + 3 * NDELTA * 512;

    const int kq = lane >> 3;       // 0..3
    const int fq = lane & 7;        // 0..7
    const int fb = fq << 3;         // bf16 element offset within a 64-elem chunk
    const __nv_bfloat162 zz = __float2bfloat162_rn(0.f);
    const uint4* wrow = (const uint4*)&wts[0][0];   // 64 uint4 per head row

    const int kbeg = warp * 24;
    for (int k0 = kbeg; k0 < kbeg + 24; k0 += 4) {
        if (k0 >= slen) continue;   // warp-uniform; masked region never read
        const int k = k0 + kq;
        const int sk = ps[k], ek = pev[k];
        const __nv_bfloat16* r0 = g0 + (((sq - sk + 191) << 9) + fb);
        const __nv_bfloat16* r1 = g1 + (((sq - ek + 191) << 9) + fb);
        const __nv_bfloat16* r2 = g2 + (((eq - sk + 191) << 9) + fb);
        const __nv_bfloat16* r3 = g3 + (((eq - ek + 191) << 9) + fb);

        __nv_bfloat162 acc[8];
        #pragma unroll
        for (int n = 0; n < 8; n++) acc[n] = zz;

        #pragma unroll 2
        for (int c = 0; c < 8; c++) {
            uint4 u0 = *(const uint4*)(r0 + (c << 6));
            uint4 u1 = *(const uint4*)(r1 + (c << 6));
            uint4 u2 = *(const uint4*)(r2 + (c << 6));
            uint4 u3 = *(const uint4*)(r3 + (c << 6));
            const __nv_bfloat162* A2 = (const __nv_bfloat162*)&u0;
            const __nv_bfloat162* B2 = (const __nv_bfloat162*)&u1;
            const __nv_bfloat162* C2 = (const __nv_bfloat162*)&u2;
            const __nv_bfloat162* D2 = (const __nv_bfloat162*)&u3;
            __nv_bfloat162 z[4];
            #pragma unroll
            for (int j = 0; j < 4; j++)
                z[j] = __hmax2(__hadd2(__hadd2(A2[j], B2[j]),
                                       __hadd2(C2[j], D2[j])), zz);
            #pragma unroll
            for (int n = 0; n < 8; n++) {
                uint4 w = wrow[(n << 6) + (c << 3) + fq];
                const __nv_bfloat162* W2 = (const __nv_bfloat162*)&w;
                acc[n] = __hfma2(z[0], W2[0], acc[n]);
                acc[n] = __hfma2(z[1], W2[1], acc[n]);
                acc[n] = __hfma2(z[2], W2[2], acc[n]);
                acc[n] = __hfma2(z[3], W2[3], acc[n]);
            }
        }

        #pragma unroll
        for (int n = 0; n < 8; n++) {
            float2 f2 = __bfloat1622float2(acc[n]);
            float s = f2.x + f2.y;
            s += __shfl_xor_sync(0xffffffffu, s, 4);
            s += __shfl_xor_sync(0xffffffffu, s, 2);
            s += __shfl_xor_sync(0xffffffffu, s, 1);
            if (fq == 0) sc[n][k] = s;
        }
    }
    __syncthreads();

    // softmax: warp n handles head n over 192 keys (6 per lane);
    // write normalized weights straight to gmem [b][n][q][k].
    {
        float vals[6];
        float mx = -1e30f;
        #pragma unroll
        for (int j = 0; j < 6; j++) {
            int k = lane + (j << 5);
            float v = (sc[warp][k] + sA[warp][k] + cd[warp]) * 0.125f;
            v = (k < slen) ? v : -1e30f;
            vals[j] = v;
            mx = fmaxf(mx, v);
        }
        #pragma unroll
        for (int s = 16; s > 0; s >>= 1)
            mx = fmaxf(mx, __shfl_xor_sync(0xffffffffu, mx, s));
        float se = 0.f;
        float ev[6];
        #pragma unroll
        for (int j = 0; j < 6; j++) {
            ev[j] = (vals[j] > -1e29f) ? __expf(vals[j] - mx) : 0.f;
            se += ev[j];
        }
        #pragma unroll
        for (int s = 16; s > 0; s >>= 1)
            se += __shfl_xor_sync(0xffffffffu, se, s);
        float inv = 1.f / se;
        float* arow = atbuf + ((size_t)(b * 8 + warp) * 192 + qi) * 192;
        #pragma unroll
        for (int j = 0; j < 6; j++)
            arow[lane + (j << 5)] = ev[j] * inv;
    }
}

// ---------------- launch ----------------
extern "C" void kernel_launch(void* const* d_in, const int* in_sizes, int n_in,
                              void* d_out, int out_size)
{
    // optional scalar lex_num at index 4
    int off = (n_in > 4 && in_sizes[4] == 1) ? 1 : 0;

    const float* key   = (const float*)d_in[0];
    const float* query = (const float*)d_in[1];
    const float* value = (const float*)d_in[2];
    const int*   seqlp = (const int*)  d_in[3];
    const int*   pos_s = (const int*)  d_in[4 + off];
    const int*   pos_e = (const int*)  d_in[5 + off];
    const float* pe    = (const float*)d_in[6 + off];
    const float* W_fus = (const float*)d_in[7 + off];
    const float* b_fus = (const float*)d_in[8 + off];
    const float* Wk    = (const float*)d_in[9 + off];
    const float* bk    = (const float*)d_in[10 + off];
    const float* Wq    = (const float*)d_in[11 + off];
    const float* bq    = (const float*)d_in[12 + off];
    const float* Wv    = (const float*)d_in[13 + off];
    const float* bv    = (const float*)d_in[14 + off];
    const float* Wr    = (const float*)d_in[15 + off];
    const float* br    = (const float*)d_in[16 + off];
    const float* ub    = (const float*)d_in[17 + off];
    const float* vb    = (const float*)d_in[18 + off];
    const float* Wff   = (const float*)d_in[19 + off];
    const float* bff   = (const float*)d_in[20 + off];
    float* out = (float*)d_out;

    float *p_q, *p_k, *p_v, *p_qv, *p_qu, *p_cd, *p_sa, *p_at, *p_x;
    __nv_bfloat16 *p_gt, *p_wt;
    cudaGetSymbolAddress((void**)&p_q,  g_q);
    cudaGetSymbolAddress((void**)&p_k,  g_k);
    cudaGetSymbolAddress((void**)&p_v,  g_v);
    cudaGetSymbolAddress((void**)&p_qv, g_qv);
    cudaGetSymbolAddress((void**)&p_qu, g_qu);
    cudaGetSymbolAddress((void**)&p_gt, g_gt);
    cudaGetSymbolAddress((void**)&p_wt, g_wt);
    cudaGetSymbolAddress((void**)&p_cd, g_cd);
    cudaGetSymbolAddress((void**)&p_sa, g_sa);
    cudaGetSymbolAddress((void**)&p_at, g_at);
    cudaGetSymbolAddress((void**)&p_x,  g_x);

    // 1) combined: q/k/v projections (K=512) + 4 delta tables (K=256, bf16 out)
    {
        DescArr24 gd = {};
        const float* Aq[3]  = {query, key, value};
        const float* Wq3[3] = {Wq, Wk, Wv};
        const float* bq3[3] = {bq, bk, bv};
        float* Cq[3] = {p_q, p_k, p_v};
        for (int i = 0; i < 3; i++) {
            gd.d[i] = {Aq[i], Wq3[i], bq3[i], Cq[i],
                       512, 1, 512, 1, 512, BL, 512, 512, 0, 0};
        }
        // g_t[di][f] = pe[di+321, :256] . W_fus[f, t*256 : (t+1)*256] (+b_fus on t=0)
        for (int t = 0; t < 4; t++) {
            gd.d[3 + t] = {pe + 321 * 512, W_fus + t * 256,
                           (t == 0) ? b_fus : nullptr,
                           p_gt + (size_t)t * NDELTA * 512,
                           512, 1, 1024, 1, 512, NDELTA, 512, 256, 1, 0};
        }
        sgemm_b<<<dim3(8, 12, 7), 256>>>(gd);
    }

    // 2) fused qv = q+v_bias, qu = q+u_bias, constD = qv.br per head
    qvqucd_kernel<<<BL, 512>>>(p_q, vb, ub, br, p_qv, p_qu, p_cd);

    // 3) combined: W~ (8 descs, bf16 out, bswap) + scoresA (16 descs)
    {
        DescArr24 gd = {};
        // W~[bq,n,f] = sum_d qv[bq, n*64+d] * Wr[n*64+d, f]  (B=Wr: b_sn=1 -> bswap)
        for (int nh = 0; nh < 8; nh++) {
            gd.d[nh] = {p_qv + nh * 64, Wr + (size_t)nh * 64 * 512, nullptr,
                        p_wt + nh * 512,
                        512, 1, 1, 512, 4096, BL, 512, 64, 1, 1};
        }
        // scoresA[b,n,q,k] = sum_d qu[b,q,n*64+d] * k[b,k,n*64+d]
        for (int b2 = 0; b2 < 2; b2++) {
            for (int nh = 0; nh < 8; nh++) {
                int z = 8 + b2 * 8 + nh;
                gd.d[z] = {p_qu + (size_t)b2 * LL * 512 + nh * 64,
                           p_k  + (size_t)b2 * LL * 512 + nh * 64,
                           nullptr,
                           p_sa + (size_t)(b2 * 8 + nh) * LL * LL,
                           512, 1, 512, 1, LL, LL, LL, 64, 0, 0};
            }
        }
        sgemm_b<<<dim3(8, 12, 24), 256>>>(gd);
    }

    // 4) fused score kernel: bf16 gathers + bf16 W~ dot + softmax -> attn wts
    attn_kernel<<<BL, 256>>>(p_gt, p_wt, p_sa, p_cd,
                             pos_s, pos_e, seqlp, p_at);

    // 5) attn@v as 16 batched GEMMs (B=v: b_sn=1 -> bswap)
    {
        DescArr24 gd = {};
        for (int b2 = 0; b2 < 2; b2++) {
            for (int nh = 0; nh < 8; nh++) {
                int z = b2 * 8 + nh;
                gd.d[z] = {p_at + (size_t)(b2 * 8 + nh) * LL * LL,
                           p_v + (size_t)b2 * LL * 512 + nh * 64,
                           nullptr,
                           p_x + (size_t)b2 * LL * 512 + nh * 64,
                           LL, 1, 1, 512, 512, LL, 64, LL, 0, 1};
            }
        }
        sgemm_b<<<dim3(1, 6, 16), 256>>>(gd);
    }

    // 6) final: out = X @ Wff^T + bff
    {
        DescArr24 gd = {};
        gd.d[0] = {p_x, Wff, bff, out, 512, 1, 512, 1, 512, BL, 512, 512, 0, 0};
        sgemm_b<<<dim3(8, 12, 1), 256>>>(gd);
    }
}